// round 2
// baseline (speedup 1.0000x reference)
#include <cuda_runtime.h>
#include <cstdint>

#define IN_F 128
#define OUT_F 64
#define MAX_N 100000
#define ALPHAF 10.0f

// Scratch (allocation-free rule: __device__ globals)
__device__ float g_deg[MAX_N];
__device__ float g_h[(size_t)MAX_N * OUT_F];

// ---------------------------------------------------------------------------
// Kernel 1: zero degree accumulator
// ---------------------------------------------------------------------------
__global__ void zero_deg_kernel(int n) {
    int i = blockIdx.x * blockDim.x + threadIdx.x;
    if (i < n) g_deg[i] = 0.0f;
}

// ---------------------------------------------------------------------------
// Kernel 2: deg[dst] += leaky_relu(edge_weight[e_feat-1] * ALPHA)
// ---------------------------------------------------------------------------
__global__ void deg_kernel(const int* __restrict__ dst,
                           const int* __restrict__ efeat,
                           const float* __restrict__ edge_weight,
                           int E) {
    int e = blockIdx.x * blockDim.x + threadIdx.x;
    if (e >= E) return;
    float w = edge_weight[efeat[e] - 1] * ALPHAF;
    w = (w > 0.0f) ? w : 0.01f * w;
    atomicAdd(&g_deg[dst[e]], w);
}

// ---------------------------------------------------------------------------
// Kernel 3: GEMM  feat_root = feat @ weight
//           out = feat_root + bias ;  h = feat_root * (1/max(deg,1))
// Tile: 64 rows x 64 cols (full OUT), K=128 in one shot.
// Block (16,16), each thread a 4x4 micro-tile.
// ---------------------------------------------------------------------------
__global__ __launch_bounds__(256) void gemm_kernel(
    const float* __restrict__ feat,
    const float* __restrict__ weight,
    const float* __restrict__ bias,
    float* __restrict__ out,
    int n)
{
    __shared__ float sA[64][IN_F + 1];   // +1 pad: kill bank conflicts on row-broadcast
    __shared__ float sB[IN_F][OUT_F];    // float4-read along columns, conflict-free

    const int tid = threadIdx.y * 16 + threadIdx.x;
    const int rowBase = blockIdx.x * 64;

    // Load A tile: 64x128 floats = 2048 float4, 8 per thread
    #pragma unroll
    for (int it = 0; it < 8; it++) {
        int idx = tid + it * 256;             // 0..2047
        int r = idx >> 5;                     // /32
        int c4 = idx & 31;                    // float4 column
        float4 v = make_float4(0.f, 0.f, 0.f, 0.f);
        int gr = rowBase + r;
        if (gr < n)
            v = reinterpret_cast<const float4*>(feat)[(size_t)gr * (IN_F / 4) + c4];
        sA[r][c4 * 4 + 0] = v.x;
        sA[r][c4 * 4 + 1] = v.y;
        sA[r][c4 * 4 + 2] = v.z;
        sA[r][c4 * 4 + 3] = v.w;
    }
    // Load B tile: 128x64 floats = 2048 float4, 8 per thread
    #pragma unroll
    for (int it = 0; it < 8; it++) {
        int idx = tid + it * 256;
        int r = idx >> 4;                     // /16
        int c4 = idx & 15;
        float4 v = reinterpret_cast<const float4*>(weight)[(size_t)r * (OUT_F / 4) + c4];
        *reinterpret_cast<float4*>(&sB[r][c4 * 4]) = v;
    }
    __syncthreads();

    float acc[4][4];
    #pragma unroll
    for (int i = 0; i < 4; i++)
        #pragma unroll
        for (int j = 0; j < 4; j++) acc[i][j] = 0.0f;

    const int ty4 = threadIdx.y * 4;
    const int tx4 = threadIdx.x * 4;

    #pragma unroll 4
    for (int k = 0; k < IN_F; k++) {
        float a0 = sA[ty4 + 0][k];
        float a1 = sA[ty4 + 1][k];
        float a2 = sA[ty4 + 2][k];
        float a3 = sA[ty4 + 3][k];
        float4 b = *reinterpret_cast<const float4*>(&sB[k][tx4]);
        acc[0][0] += a0 * b.x; acc[0][1] += a0 * b.y; acc[0][2] += a0 * b.z; acc[0][3] += a0 * b.w;
        acc[1][0] += a1 * b.x; acc[1][1] += a1 * b.y; acc[1][2] += a1 * b.z; acc[1][3] += a1 * b.w;
        acc[2][0] += a2 * b.x; acc[2][1] += a2 * b.y; acc[2][2] += a2 * b.z; acc[2][3] += a2 * b.w;
        acc[3][0] += a3 * b.x; acc[3][1] += a3 * b.y; acc[3][2] += a3 * b.z; acc[3][3] += a3 * b.w;
    }

    float4 bi = *reinterpret_cast<const float4*>(&bias[tx4]);

    #pragma unroll
    for (int i = 0; i < 4; i++) {
        int gr = rowBase + ty4 + i;
        if (gr >= n) break;
        float d = g_deg[gr];
        float norm = 1.0f / fmaxf(d, 1.0f);
        float4 fr = make_float4(acc[i][0], acc[i][1], acc[i][2], acc[i][3]);
        float4 o  = make_float4(fr.x + bi.x, fr.y + bi.y, fr.z + bi.z, fr.w + bi.w);
        float4 hh = make_float4(fr.x * norm, fr.y * norm, fr.z * norm, fr.w * norm);
        reinterpret_cast<float4*>(out)[(size_t)gr * (OUT_F / 4) + (tx4 >> 2)] = o;
        reinterpret_cast<float4*>(g_h)[(size_t)gr * (OUT_F / 4) + (tx4 >> 2)] = hh;
    }
}

// ---------------------------------------------------------------------------
// Kernel 4: edge aggregation  out[dst] += h[src] * ew   (16 threads per edge,
// one float4 each, vectorized L2 reduction red.global.add.v4.f32)
// ---------------------------------------------------------------------------
__global__ __launch_bounds__(256) void agg_kernel(
    const int* __restrict__ src,
    const int* __restrict__ dst,
    const int* __restrict__ efeat,
    const float* __restrict__ edge_weight,
    float* __restrict__ out,
    int E)
{
    unsigned gid = blockIdx.x * blockDim.x + threadIdx.x;
    int e = gid >> 4;
    int lane = gid & 15;
    if (e >= E) return;

    int s = src[e];
    int d = dst[e];
    float w = edge_weight[efeat[e] - 1] * ALPHAF;
    w = (w > 0.0f) ? w : 0.01f * w;

    float4 hv = reinterpret_cast<const float4*>(g_h)[(size_t)s * (OUT_F / 4) + lane];
    float4 v = make_float4(hv.x * w, hv.y * w, hv.z * w, hv.w * w);

    float* p = out + (size_t)d * OUT_F + lane * 4;
    asm volatile("red.global.add.v4.f32 [%0], {%1, %2, %3, %4};"
                 :: "l"(p), "f"(v.x), "f"(v.y), "f"(v.z), "f"(v.w)
                 : "memory");
}

// ---------------------------------------------------------------------------
// Launch
// ---------------------------------------------------------------------------
extern "C" void kernel_launch(void* const* d_in, const int* in_sizes, int n_in,
                              void* d_out, int out_size) {
    const float* feat        = (const float*)d_in[0];
    const float* edge_weight = (const float*)d_in[1];
    const float* weight      = (const float*)d_in[2];
    const float* bias        = (const float*)d_in[3];
    const int*   src         = (const int*)d_in[4];
    const int*   dst         = (const int*)d_in[5];
    const int*   efeat       = (const int*)d_in[6];
    float* out = (float*)d_out;

    int n = in_sizes[0] / IN_F;
    int E = in_sizes[4];

    zero_deg_kernel<<<(n + 255) / 256, 256>>>(n);
    deg_kernel<<<(E + 255) / 256, 256>>>(dst, efeat, edge_weight, E);

    dim3 gblk(16, 16);
    gemm_kernel<<<(n + 63) / 64, gblk>>>(feat, weight, bias, out, n);

    unsigned total = (unsigned)E * 16u;
    agg_kernel<<<(total + 255) / 256, 256>>>(src, dst, efeat, edge_weight, out, E);
}

// round 5
// speedup vs baseline: 1.1121x; 1.1121x over previous
#include <cuda_runtime.h>
#include <cstdint>

#define IN_F 128
#define OUT_F 64
#define MAX_N 100000
#define MAX_E 1600000
#define ALPHAF 10.0f

// Scratch (allocation-free rule: __device__ globals)
__device__ int   g_cnt[MAX_N];       // per-dst in-degree counts
__device__ int   g_rowstart[MAX_N];  // CSR row offsets (exclusive prefix of cnt)
__device__ int   g_cursor[MAX_N];    // scatter cursors (mutated copy of rowstart)
__device__ int   g_blksum[128];      // scan block sums
__device__ float g_deg[MAX_N];       // sum of incoming edge weights
__device__ float g_h[(size_t)MAX_N * OUT_F];       // normalized transformed feats
__device__ int2  g_edge[MAX_E];      // CSR payload: (src, bitcast(w))

// ---------------------------------------------------------------------------
// K1: zero counters + deg
// ---------------------------------------------------------------------------
__global__ void zero_kernel(int n) {
    int i = blockIdx.x * blockDim.x + threadIdx.x;
    if (i < n) { g_cnt[i] = 0; g_deg[i] = 0.0f; }
}

// ---------------------------------------------------------------------------
// K2: histogram of dst
// ---------------------------------------------------------------------------
__global__ void hist_kernel(const int* __restrict__ dst, int E) {
    int e = blockIdx.x * blockDim.x + threadIdx.x;
    if (e < E) atomicAdd(&g_cnt[dst[e]], 1);
}

// ---------------------------------------------------------------------------
// K3a: block-local exclusive scan (block covers 2048 elems, 8 per thread)
// ---------------------------------------------------------------------------
__global__ __launch_bounds__(256) void scan1_kernel(int n) {
    __shared__ int s[256];
    const int tid = threadIdx.x;
    const int base = blockIdx.x * 2048 + tid * 8;

    int v[8];
    int tsum = 0;
    #pragma unroll
    for (int j = 0; j < 8; j++) {
        int idx = base + j;
        int c = (idx < n) ? g_cnt[idx] : 0;
        v[j] = tsum;          // exclusive prefix within thread
        tsum += c;
    }
    s[tid] = tsum;
    __syncthreads();
    // inclusive scan of thread sums
    #pragma unroll
    for (int off = 1; off < 256; off <<= 1) {
        int t = 0;
        if (tid >= off) t = s[tid - off];
        __syncthreads();
        if (tid >= off) s[tid] += t;
        __syncthreads();
    }
    int texcl = s[tid] - tsum;   // exclusive prefix of this thread's sum
    #pragma unroll
    for (int j = 0; j < 8; j++) {
        int idx = base + j;
        if (idx < n) g_rowstart[idx] = texcl + v[j];   // block-local for now
    }
    if (tid == 255) g_blksum[blockIdx.x] = s[255];
}

// ---------------------------------------------------------------------------
// K3b: scan the block sums (tiny)
// ---------------------------------------------------------------------------
__global__ void scan2_kernel(int nb) {
    if (threadIdx.x == 0 && blockIdx.x == 0) {
        int run = 0;
        for (int b = 0; b < nb; b++) {
            int t = g_blksum[b];
            g_blksum[b] = run;
            run += t;
        }
    }
}

// ---------------------------------------------------------------------------
// K3c: add block offsets; init cursor = rowstart
// ---------------------------------------------------------------------------
__global__ __launch_bounds__(256) void scan3_kernel(int n) {
    const int base = blockIdx.x * 2048 + threadIdx.x * 8;
    int off = g_blksum[blockIdx.x];
    #pragma unroll
    for (int j = 0; j < 8; j++) {
        int idx = base + j;
        if (idx < n) {
            int r = g_rowstart[idx] + off;
            g_rowstart[idx] = r;
            g_cursor[idx] = r;
        }
    }
}

// ---------------------------------------------------------------------------
// K4: scatter edges into CSR slots; fuse deg accumulation
// ---------------------------------------------------------------------------
__global__ void scatter_kernel(const int* __restrict__ src,
                               const int* __restrict__ dst,
                               const int* __restrict__ efeat,
                               const float* __restrict__ edge_weight,
                               int E) {
    int e = blockIdx.x * blockDim.x + threadIdx.x;
    if (e >= E) return;
    int d = dst[e];
    float w = edge_weight[efeat[e] - 1] * ALPHAF;
    w = (w > 0.0f) ? w : 0.01f * w;
    int p = atomicAdd(&g_cursor[d], 1);
    g_edge[p] = make_int2(src[e], __float_as_int(w));
    atomicAdd(&g_deg[d], w);
}

// ---------------------------------------------------------------------------
// K5: GEMM  fr = feat @ weight ;  out = fr + bias ;  g_h = fr / max(deg,1)
// ---------------------------------------------------------------------------
__global__ __launch_bounds__(256) void gemm_kernel(
    const float* __restrict__ feat,
    const float* __restrict__ weight,
    const float* __restrict__ bias,
    float* __restrict__ out,
    int n)
{
    __shared__ float sA[64][IN_F + 1];
    __shared__ float sB[IN_F][OUT_F];

    const int tid = threadIdx.y * 16 + threadIdx.x;
    const int rowBase = blockIdx.x * 64;

    #pragma unroll
    for (int it = 0; it < 8; it++) {
        int idx = tid + it * 256;
        int r = idx >> 5;
        int c4 = idx & 31;
        float4 v = make_float4(0.f, 0.f, 0.f, 0.f);
        int gr = rowBase + r;
        if (gr < n)
            v = reinterpret_cast<const float4*>(feat)[(size_t)gr * (IN_F / 4) + c4];
        sA[r][c4 * 4 + 0] = v.x;
        sA[r][c4 * 4 + 1] = v.y;
        sA[r][c4 * 4 + 2] = v.z;
        sA[r][c4 * 4 + 3] = v.w;
    }
    #pragma unroll
    for (int it = 0; it < 8; it++) {
        int idx = tid + it * 256;
        int r = idx >> 4;
        int c4 = idx & 15;
        float4 v = reinterpret_cast<const float4*>(weight)[(size_t)r * (OUT_F / 4) + c4];
        *reinterpret_cast<float4*>(&sB[r][c4 * 4]) = v;
    }
    __syncthreads();

    float acc[4][4];
    #pragma unroll
    for (int i = 0; i < 4; i++)
        #pragma unroll
        for (int j = 0; j < 4; j++) acc[i][j] = 0.0f;

    const int ty4 = threadIdx.y * 4;
    const int tx4 = threadIdx.x * 4;

    #pragma unroll 4
    for (int k = 0; k < IN_F; k++) {
        float a0 = sA[ty4 + 0][k];
        float a1 = sA[ty4 + 1][k];
        float a2 = sA[ty4 + 2][k];
        float a3 = sA[ty4 + 3][k];
        float4 b = *reinterpret_cast<const float4*>(&sB[k][tx4]);
        acc[0][0] += a0 * b.x; acc[0][1] += a0 * b.y; acc[0][2] += a0 * b.z; acc[0][3] += a0 * b.w;
        acc[1][0] += a1 * b.x; acc[1][1] += a1 * b.y; acc[1][2] += a1 * b.z; acc[1][3] += a1 * b.w;
        acc[2][0] += a2 * b.x; acc[2][1] += a2 * b.y; acc[2][2] += a2 * b.z; acc[2][3] += a2 * b.w;
        acc[3][0] += a3 * b.x; acc[3][1] += a3 * b.y; acc[3][2] += a3 * b.z; acc[3][3] += a3 * b.w;
    }

    float4 bi = *reinterpret_cast<const float4*>(&bias[tx4]);

    #pragma unroll
    for (int i = 0; i < 4; i++) {
        int gr = rowBase + ty4 + i;
        if (gr >= n) break;
        float d = g_deg[gr];
        float norm = 1.0f / fmaxf(d, 1.0f);
        float4 fr = make_float4(acc[i][0], acc[i][1], acc[i][2], acc[i][3]);
        float4 o  = make_float4(fr.x + bi.x, fr.y + bi.y, fr.z + bi.z, fr.w + bi.w);
        float4 hh = make_float4(fr.x * norm, fr.y * norm, fr.z * norm, fr.w * norm);
        reinterpret_cast<float4*>(out)[(size_t)gr * (OUT_F / 4) + (tx4 >> 2)] = o;
        reinterpret_cast<float4*>(g_h)[(size_t)gr * (OUT_F / 4) + (tx4 >> 2)] = hh;
    }
}

// ---------------------------------------------------------------------------
// K6: pull-gather. 16 threads per dst node, register accumulation, no atomics.
// ---------------------------------------------------------------------------
__global__ __launch_bounds__(256) void gather_kernel(float* __restrict__ out, int n)
{
    int node = blockIdx.x * 16 + (threadIdx.x >> 4);
    int lane = threadIdx.x & 15;
    if (node >= n) return;

    int st = g_rowstart[node];
    int en = st + g_cnt[node];

    float4 acc = make_float4(0.f, 0.f, 0.f, 0.f);
    const float4* hp = reinterpret_cast<const float4*>(g_h);

    int i = st;
    // unroll-by-2: two independent gathers in flight
    for (; i + 1 < en; i += 2) {
        int2 e0 = g_edge[i];
        int2 e1 = g_edge[i + 1];
        float w0 = __int_as_float(e0.y);
        float w1 = __int_as_float(e1.y);
        float4 h0 = hp[(size_t)e0.x * 16 + lane];
        float4 h1 = hp[(size_t)e1.x * 16 + lane];
        acc.x += h0.x * w0 + h1.x * w1;
        acc.y += h0.y * w0 + h1.y * w1;
        acc.z += h0.z * w0 + h1.z * w1;
        acc.w += h0.w * w0 + h1.w * w1;
    }
    if (i < en) {
        int2 e0 = g_edge[i];
        float w0 = __int_as_float(e0.y);
        float4 h0 = hp[(size_t)e0.x * 16 + lane];
        acc.x += h0.x * w0;
        acc.y += h0.y * w0;
        acc.z += h0.z * w0;
        acc.w += h0.w * w0;
    }

    float4* op = reinterpret_cast<float4*>(out) + (size_t)node * 16 + lane;
    float4 o = *op;   // out already holds fr + bias from GEMM
    o.x += acc.x; o.y += acc.y; o.z += acc.z; o.w += acc.w;
    *op = o;
}

// ---------------------------------------------------------------------------
// Launch
// ---------------------------------------------------------------------------
extern "C" void kernel_launch(void* const* d_in, const int* in_sizes, int n_in,
                              void* d_out, int out_size) {
    const float* feat        = (const float*)d_in[0];
    const float* edge_weight = (const float*)d_in[1];
    const float* weight      = (const float*)d_in[2];
    const float* bias        = (const float*)d_in[3];
    const int*   src         = (const int*)d_in[4];
    const int*   dst         = (const int*)d_in[5];
    const int*   efeat       = (const int*)d_in[6];
    float* out = (float*)d_out;

    int n = in_sizes[0] / IN_F;
    int E = in_sizes[4];
    int nb = (n + 2047) / 2048;

    zero_kernel<<<(n + 255) / 256, 256>>>(n);
    hist_kernel<<<(E + 255) / 256, 256>>>(dst, E);
    scan1_kernel<<<nb, 256>>>(n);
    scan2_kernel<<<1, 32>>>(nb);
    scan3_kernel<<<nb, 256>>>(n);
    scatter_kernel<<<(E + 255) / 256, 256>>>(src, dst, efeat, edge_weight, E);

    dim3 gblk(16, 16);
    gemm_kernel<<<(n + 63) / 64, gblk>>>(feat, weight, bias, out, n);

    gather_kernel<<<(n + 15) / 16, 256>>>(out, n);
}

// round 6
// speedup vs baseline: 1.1876x; 1.0679x over previous
#include <cuda_runtime.h>
#include <cuda_bf16.h>
#include <cstdint>

#define IN_F 128
#define OUT_F 64
#define MAX_N 100000
#define MAX_E 1600000
#define ALPHAF 10.0f

// Scratch (allocation-free rule: __device__ globals)
__device__ int      g_cnt[MAX_N];        // per-dst in-degree counts
__device__ int      g_rowstart[MAX_N];   // CSR row offsets
__device__ int      g_cursor[MAX_N];     // scatter cursors
__device__ int      g_blksum[128];       // scan block sums
__device__ float    g_deg[MAX_N];        // sum of incoming edge weights
__device__ unsigned g_h16[(size_t)MAX_N * (OUT_F / 2)];  // h rows in bf16 (2 per uint)
__device__ unsigned g_epack[MAX_E];      // packed edge: src | (etype<<17)

// ---------------------------------------------------------------------------
// K1: zero counters + deg
// ---------------------------------------------------------------------------
__global__ void zero_kernel(int n) {
    int i = blockIdx.x * blockDim.x + threadIdx.x;
    if (i < n) { g_cnt[i] = 0; g_deg[i] = 0.0f; }
}

// ---------------------------------------------------------------------------
// K2: histogram of dst + fused deg accumulation
// ---------------------------------------------------------------------------
__global__ void hist_kernel(const int* __restrict__ dst,
                            const int* __restrict__ efeat,
                            const float* __restrict__ edge_weight,
                            int E) {
    int e = blockIdx.x * blockDim.x + threadIdx.x;
    if (e >= E) return;
    int d = dst[e];
    float w = edge_weight[efeat[e] - 1] * ALPHAF;
    w = (w > 0.0f) ? w : 0.01f * w;
    atomicAdd(&g_cnt[d], 1);
    atomicAdd(&g_deg[d], w);
}

// ---------------------------------------------------------------------------
// K3a: block-local exclusive scan (block covers 2048 elems, 8 per thread)
// ---------------------------------------------------------------------------
__global__ __launch_bounds__(256) void scan1_kernel(int n) {
    __shared__ int s[256];
    const int tid = threadIdx.x;
    const int base = blockIdx.x * 2048 + tid * 8;

    int v[8];
    int tsum = 0;
    #pragma unroll
    for (int j = 0; j < 8; j++) {
        int idx = base + j;
        int c = (idx < n) ? g_cnt[idx] : 0;
        v[j] = tsum;
        tsum += c;
    }
    s[tid] = tsum;
    __syncthreads();
    #pragma unroll
    for (int off = 1; off < 256; off <<= 1) {
        int t = 0;
        if (tid >= off) t = s[tid - off];
        __syncthreads();
        if (tid >= off) s[tid] += t;
        __syncthreads();
    }
    int texcl = s[tid] - tsum;
    #pragma unroll
    for (int j = 0; j < 8; j++) {
        int idx = base + j;
        if (idx < n) g_rowstart[idx] = texcl + v[j];   // block-local for now
    }
    if (tid == 255) g_blksum[blockIdx.x] = s[255];
}

// ---------------------------------------------------------------------------
// K3b: finalize offsets; each block computes its own block-sum prefix
// (nb <= 128, so the scan2 kernel is gone)
// ---------------------------------------------------------------------------
__global__ __launch_bounds__(256) void scan3_kernel(int n) {
    __shared__ int s_off;
    if (threadIdx.x == 0) s_off = 0;
    __syncthreads();
    if (threadIdx.x < 128 && threadIdx.x < blockIdx.x)
        atomicAdd(&s_off, g_blksum[threadIdx.x]);
    __syncthreads();
    int off = s_off;

    const int base = blockIdx.x * 2048 + threadIdx.x * 8;
    #pragma unroll
    for (int j = 0; j < 8; j++) {
        int idx = base + j;
        if (idx < n) {
            int r = g_rowstart[idx] + off;
            g_rowstart[idx] = r;
            g_cursor[idx] = r;
        }
    }
}

// ---------------------------------------------------------------------------
// K4: scatter packed edges into CSR slots (src 17 bits | etype 3 bits)
// ---------------------------------------------------------------------------
__global__ void scatter_kernel(const int* __restrict__ src,
                               const int* __restrict__ dst,
                               const int* __restrict__ efeat,
                               int E) {
    int e = blockIdx.x * blockDim.x + threadIdx.x;
    if (e >= E) return;
    int d = dst[e];
    int p = atomicAdd(&g_cursor[d], 1);
    g_epack[p] = (unsigned)src[e] | ((unsigned)(efeat[e] - 1) << 17);
}

// ---------------------------------------------------------------------------
// K5: GEMM  fr = feat @ weight ;  out = fr + bias ;  g_h16 = bf16(fr/max(deg,1))
// ---------------------------------------------------------------------------
__global__ __launch_bounds__(256) void gemm_kernel(
    const float* __restrict__ feat,
    const float* __restrict__ weight,
    const float* __restrict__ bias,
    float* __restrict__ out,
    int n)
{
    __shared__ float sA[64][IN_F + 1];
    __shared__ float sB[IN_F][OUT_F];

    const int tid = threadIdx.y * 16 + threadIdx.x;
    const int rowBase = blockIdx.x * 64;

    #pragma unroll
    for (int it = 0; it < 8; it++) {
        int idx = tid + it * 256;
        int r = idx >> 5;
        int c4 = idx & 31;
        float4 v = make_float4(0.f, 0.f, 0.f, 0.f);
        int gr = rowBase + r;
        if (gr < n)
            v = reinterpret_cast<const float4*>(feat)[(size_t)gr * (IN_F / 4) + c4];
        sA[r][c4 * 4 + 0] = v.x;
        sA[r][c4 * 4 + 1] = v.y;
        sA[r][c4 * 4 + 2] = v.z;
        sA[r][c4 * 4 + 3] = v.w;
    }
    #pragma unroll
    for (int it = 0; it < 8; it++) {
        int idx = tid + it * 256;
        int r = idx >> 4;
        int c4 = idx & 15;
        float4 v = reinterpret_cast<const float4*>(weight)[(size_t)r * (OUT_F / 4) + c4];
        *reinterpret_cast<float4*>(&sB[r][c4 * 4]) = v;
    }
    __syncthreads();

    float acc[4][4];
    #pragma unroll
    for (int i = 0; i < 4; i++)
        #pragma unroll
        for (int j = 0; j < 4; j++) acc[i][j] = 0.0f;

    const int ty4 = threadIdx.y * 4;
    const int tx4 = threadIdx.x * 4;

    #pragma unroll 4
    for (int k = 0; k < IN_F; k++) {
        float a0 = sA[ty4 + 0][k];
        float a1 = sA[ty4 + 1][k];
        float a2 = sA[ty4 + 2][k];
        float a3 = sA[ty4 + 3][k];
        float4 b = *reinterpret_cast<const float4*>(&sB[k][tx4]);
        acc[0][0] += a0 * b.x; acc[0][1] += a0 * b.y; acc[0][2] += a0 * b.z; acc[0][3] += a0 * b.w;
        acc[1][0] += a1 * b.x; acc[1][1] += a1 * b.y; acc[1][2] += a1 * b.z; acc[1][3] += a1 * b.w;
        acc[2][0] += a2 * b.x; acc[2][1] += a2 * b.y; acc[2][2] += a2 * b.z; acc[2][3] += a2 * b.w;
        acc[3][0] += a3 * b.x; acc[3][1] += a3 * b.y; acc[3][2] += a3 * b.z; acc[3][3] += a3 * b.w;
    }

    float4 bi = *reinterpret_cast<const float4*>(&bias[tx4]);

    #pragma unroll
    for (int i = 0; i < 4; i++) {
        int gr = rowBase + ty4 + i;
        if (gr >= n) break;
        float d = g_deg[gr];
        float norm = 1.0f / fmaxf(d, 1.0f);
        float4 fr = make_float4(acc[i][0], acc[i][1], acc[i][2], acc[i][3]);
        float4 o  = make_float4(fr.x + bi.x, fr.y + bi.y, fr.z + bi.z, fr.w + bi.w);
        reinterpret_cast<float4*>(out)[(size_t)gr * (OUT_F / 4) + (tx4 >> 2)] = o;

        // bf16 h row: 4 cols -> 2 packed uints (8 bytes, aligned since tx4 % 4 == 0)
        __nv_bfloat162 p0 = __floats2bfloat162_rn(fr.x * norm, fr.y * norm);
        __nv_bfloat162 p1 = __floats2bfloat162_rn(fr.z * norm, fr.w * norm);
        uint2 u;
        u.x = *reinterpret_cast<unsigned*>(&p0);
        u.y = *reinterpret_cast<unsigned*>(&p1);
        *reinterpret_cast<uint2*>(&g_h16[(size_t)gr * (OUT_F / 2) + (tx4 >> 1)]) = u;
    }
}

// ---------------------------------------------------------------------------
// K6: pull-gather. 8 threads per dst node; bf16 h rows; smem weight LUT.
// ---------------------------------------------------------------------------
__global__ __launch_bounds__(256) void gather_kernel(
    float* __restrict__ out,
    const float* __restrict__ edge_weight,
    int n)
{
    __shared__ float s_wl[8];
    if (threadIdx.x < 8) {
        float w = edge_weight[threadIdx.x] * ALPHAF;
        s_wl[threadIdx.x] = (w > 0.0f) ? w : 0.01f * w;
    }
    __syncthreads();

    int node = blockIdx.x * 32 + (threadIdx.x >> 3);
    int lane = threadIdx.x & 7;
    if (node >= n) return;

    int st = g_rowstart[node];
    int en = st + g_cnt[node];

    float acc[8];
    #pragma unroll
    for (int j = 0; j < 8; j++) acc[j] = 0.0f;

    const uint4* hp = reinterpret_cast<const uint4*>(g_h16);  // 8 uint4 per 128B row

    int i = st;
    for (; i + 1 < en; i += 2) {
        unsigned e0 = g_epack[i];
        unsigned e1 = g_epack[i + 1];
        float w0 = s_wl[e0 >> 17];
        float w1 = s_wl[e1 >> 17];
        uint4 h0 = hp[(size_t)(e0 & 0x1FFFFu) * 8 + lane];
        uint4 h1 = hp[(size_t)(e1 & 0x1FFFFu) * 8 + lane];
        const __nv_bfloat162* b0 = reinterpret_cast<const __nv_bfloat162*>(&h0);
        const __nv_bfloat162* b1 = reinterpret_cast<const __nv_bfloat162*>(&h1);
        #pragma unroll
        for (int j = 0; j < 4; j++) {
            float2 f0 = __bfloat1622float2(b0[j]);
            float2 f1 = __bfloat1622float2(b1[j]);
            acc[2 * j + 0] += f0.x * w0 + f1.x * w1;
            acc[2 * j + 1] += f0.y * w0 + f1.y * w1;
        }
    }
    if (i < en) {
        unsigned e0 = g_epack[i];
        float w0 = s_wl[e0 >> 17];
        uint4 h0 = hp[(size_t)(e0 & 0x1FFFFu) * 8 + lane];
        const __nv_bfloat162* b0 = reinterpret_cast<const __nv_bfloat162*>(&h0);
        #pragma unroll
        for (int j = 0; j < 4; j++) {
            float2 f0 = __bfloat1622float2(b0[j]);
            acc[2 * j + 0] += f0.x * w0;
            acc[2 * j + 1] += f0.y * w0;
        }
    }

    // RMW out: this lane owns 8 consecutive floats (two float4s)
    float4* op = reinterpret_cast<float4*>(out + (size_t)node * OUT_F + lane * 8);
    float4 a = op[0];
    float4 b = op[1];
    a.x += acc[0]; a.y += acc[1]; a.z += acc[2]; a.w += acc[3];
    b.x += acc[4]; b.y += acc[5]; b.z += acc[6]; b.w += acc[7];
    op[0] = a;
    op[1] = b;
}

// ---------------------------------------------------------------------------
// Launch
// ---------------------------------------------------------------------------
extern "C" void kernel_launch(void* const* d_in, const int* in_sizes, int n_in,
                              void* d_out, int out_size) {
    const float* feat        = (const float*)d_in[0];
    const float* edge_weight = (const float*)d_in[1];
    const float* weight      = (const float*)d_in[2];
    const float* bias        = (const float*)d_in[3];
    const int*   src         = (const int*)d_in[4];
    const int*   dst         = (const int*)d_in[5];
    const int*   efeat       = (const int*)d_in[6];
    float* out = (float*)d_out;

    int n = in_sizes[0] / IN_F;
    int E = in_sizes[4];
    int nb = (n + 2047) / 2048;

    zero_kernel<<<(n + 255) / 256, 256>>>(n);
    hist_kernel<<<(E + 255) / 256, 256>>>(dst, efeat, edge_weight, E);
    scan1_kernel<<<nb, 256>>>(n);
    scan3_kernel<<<nb, 256>>>(n);
    scatter_kernel<<<(E + 255) / 256, 256>>>(src, dst, efeat, E);

    dim3 gblk(16, 16);
    gemm_kernel<<<(n + 63) / 64, gblk>>>(feat, weight, bias, out, n);

    gather_kernel<<<(n + 31) / 32, 256>>>(out, edge_weight, n);
}